// round 14
// baseline (speedup 1.0000x reference)
#include <cuda_runtime.h>
#include <cuda_bf16.h>

#define NS 10
#define ND 32
#define NL 4
#define NB 1024

typedef unsigned int u32;

// cvt.rn.bf16x2.f32 d, a, b : upper16 = cvt(a), lower16 = cvt(b)
__device__ __forceinline__ u32 cvt2(float lo, float hi) {
    u32 r;
    asm("cvt.rn.bf16x2.f32 %0, %1, %2;" : "=r"(r) : "f"(hi), "f"(lo));
    return r;
}
__device__ __forceinline__ float lo_f(u32 p) { return __uint_as_float(p << 16); }
__device__ __forceinline__ float hi_f(u32 p) { return __uint_as_float(p & 0xffff0000u); }

__device__ __forceinline__ void mma_bf16(float* c, const u32* a, u32 b0, u32 b1) {
    asm volatile("mma.sync.aligned.m16n8k16.row.col.f32.bf16.bf16.f32 "
                 "{%0,%1,%2,%3}, {%4,%5,%6,%7}, {%8,%9}, {%0,%1,%2,%3};"
                 : "+f"(c[0]), "+f"(c[1]), "+f"(c[2]), "+f"(c[3])
                 : "r"(a[0]), "r"(a[1]), "r"(a[2]), "r"(a[3]), "r"(b0), "r"(b1));
}
#define LDSM_X4(r0, r1, r2, r3, addr) \
    asm volatile("ldmatrix.sync.aligned.m8n8.x4.shared.b16 {%0,%1,%2,%3}, [%4];" \
                 : "=r"(r0), "=r"(r1), "=r"(r2), "=r"(r3) : "r"(addr))

__device__ __forceinline__ u32 smem_u32(const void* p) {
    u32 a;
    asm("{ .reg .u64 t; cvta.to.shared.u64 t, %1; cvt.u32.u64 %0, t; }"
        : "=r"(a) : "l"(p));
    return a;
}

// ============================================================
// Single fused kernel. Block = 256 threads = 8 warps = (2 batch) x (4 layers).
// Warp: 32 rows (d = lane) of one (b, l). C[row, h] = Plo @ DW^T via mma.sync,
// then dend = Phi-dot on C fragments, warp/block reduce, sigmoid -> out.
// Shared (48KB exactly): A 8 warps x 32 rows x 128B (XOR-swizzled), B frags 16KB.
// ============================================================
__global__ __launch_bounds__(256, 3)
void main_kernel(const float* __restrict__ x,
                 const float* __restrict__ k,
                 const float* __restrict__ w,
                 const float* __restrict__ q,
                 const float* __restrict__ dend_w,
                 const float* __restrict__ dend_b,
                 const float* __restrict__ lin_w,
                 const float* __restrict__ lin_b,
                 const float* __restrict__ final_w,
                 const float* __restrict__ final_b,
                 const float* __restrict__ ks,
                 float* __restrict__ out)
{
    __shared__ __align__(16) unsigned char sMem[49152];
    unsigned char* sA = sMem;                                   // 32 KB
    uint4* sB = reinterpret_cast<uint4*>(sMem + 32768);         // 16 KB: [term][l][nt][lane]
    float (*sfin)[NL] = reinterpret_cast<float (*)[NL]>(sMem);  // overlay on sA (post-sync)

    const int tid  = threadIdx.x;
    const int wid  = tid >> 5, lane = tid & 31;
    const int l    = wid & 3,  bl   = wid >> 2;
    const int b    = blockIdx.x * 2 + bl;
    const int g    = lane >> 2, tq = lane & 3;
    const int sw   = lane & 7;

    // ---- B fragment staging (fused prep): 2 slots per thread, 512 slots ----
    // B[n][k] = DW[h = 8*nt + g][lo = k + 16*kt]; dwpad[0] = 0.
    #pragma unroll
    for (int j = 0; j < 2; ++j) {
        int slot   = tid * 2 + j;
        int lane_s = slot & 31;
        int nt_s   = (slot >> 5) & 3;
        int l_s    = slot >> 7;
        int tq_s   = lane_s & 3;
        int h_s    = 8 * nt_s + (lane_s >> 2);
        float v8[8];
        #pragma unroll
        for (int kt = 0; kt < 2; ++kt)
            #pragma unroll
            for (int jj = 0; jj < 4; ++jj) {
                int col = 2 * tq_s + (jj & 1) + 8 * (jj >> 1) + 16 * kt;
                int vv  = 32 * h_s + col;
                v8[kt * 4 + jj] = vv ? dend_w[l_s * 1023 + vv - 1] : 0.0f;
            }
        u32 hi4[4], lo4[4];
        #pragma unroll
        for (int p = 0; p < 4; ++p) {
            hi4[p] = cvt2(v8[2 * p], v8[2 * p + 1]);
            lo4[p] = cvt2(v8[2 * p] - lo_f(hi4[p]), v8[2 * p + 1] - hi_f(hi4[p]));
        }
        int bi = (l_s * 4 + nt_s) * 32 + lane_s;
        sB[bi]       = make_uint4(hi4[0], hi4[1], hi4[2], hi4[3]);   // term 0 block
        sB[512 + bi] = make_uint4(lo4[0], lo4[1], lo4[2], lo4[3]);   // term 1 block
    }

    // ---- s_i = sigmoid(k*(w*x - q)), row = (l, d=lane); float2 loads ----
    float s[NS];
    {
        const float2* x2 = reinterpret_cast<const float2*>(x) + b * 5;
        const float2* k2 = reinterpret_cast<const float2*>(k) + (l * ND + lane) * 5;
        const float2* w2 = reinterpret_cast<const float2*>(w) + (l * ND + lane) * 5;
        const float2* q2 = reinterpret_cast<const float2*>(q) + (l * ND + lane) * 5;
        #pragma unroll
        for (int j = 0; j < 5; ++j) {
            float2 xx = x2[j], kk = k2[j], ww = w2[j], qq = q2[j];
            float z0 = kk.x * (ww.x * xx.x - qq.x);
            float z1 = kk.y * (ww.y * xx.y - qq.y);
            s[2 * j]     = 1.0f / (1.0f + __expf(-z0));
            s[2 * j + 1] = 1.0f / (1.0f + __expf(-z1));
        }
    }

    // ---- Plo subset products (bit p of lo -> s[9-p]) ----
    float Plo[32];
    Plo[0] = 1.0f;
    #pragma unroll
    for (int bit = 0; bit < 5; ++bit) {
        const float sv = s[9 - bit];
        #pragma unroll
        for (int u = 0; u < (1 << bit); ++u)
            Plo[(1 << bit) + u] = Plo[u] * sv;
    }

    // ---- stage A row: 128B/row, 16B chunks XOR-swizzled by (row & 7) ----
    // chunks 0..3 = bf16 hi pairs, 4..7 = residual lo pairs.
    {
        u32 hi[16], lo[16];
        #pragma unroll
        for (int c = 0; c < 16; ++c)
            hi[c] = cvt2(Plo[2 * c], Plo[2 * c + 1]);
        #pragma unroll
        for (int c = 0; c < 16; ++c)
            lo[c] = cvt2(Plo[2 * c] - lo_f(hi[c]), Plo[2 * c + 1] - hi_f(hi[c]));
        unsigned char* rb = sA + wid * 4096 + lane * 128;
        #pragma unroll
        for (int c = 0; c < 4; ++c)
            *reinterpret_cast<uint4*>(rb + ((c ^ sw) << 4)) =
                make_uint4(hi[4 * c], hi[4 * c + 1], hi[4 * c + 2], hi[4 * c + 3]);
        #pragma unroll
        for (int c = 0; c < 4; ++c)
            *reinterpret_cast<uint4*>(rb + (((c + 4) ^ sw) << 4)) =
                make_uint4(lo[4 * c], lo[4 * c + 1], lo[4 * c + 2], lo[4 * c + 3]);
    }

    // ---- Phi factors for the 4 C-fragment rows (g, g+8, g+16, g+24) ----
    // h = 8*nt + 2*tq + e : bit0=e->s4, bits1-2=tq->s3,s2, bits3-4=nt->s1,s0
    float pb[4], s4m[4], cnt1[4], cnt2[4], cnt3[4];
    #pragma unroll
    for (int m = 0; m < 4; ++m) {
        int src = g + 8 * m;
        float a0 = __shfl_sync(0xffffffffu, s[0], src);
        float a1 = __shfl_sync(0xffffffffu, s[1], src);
        float a2 = __shfl_sync(0xffffffffu, s[2], src);
        float a3 = __shfl_sync(0xffffffffu, s[3], src);
        s4m[m]   = __shfl_sync(0xffffffffu, s[4], src);
        pb[m] = ((tq & 1) ? a3 : 1.0f) * ((tq & 2) ? a2 : 1.0f);
        cnt1[m] = a1; cnt2[m] = a0; cnt3[m] = a0 * a1;
    }
    __syncthreads();   // B frags + A rows visible

    // ---- mma mainloop ----
    float dpart[4] = {0.0f, 0.0f, 0.0f, 0.0f};
    // ldmatrix lane addressing: row = lane&15 of the 16-row tile; +16B for lanes>=16
    const u32 aAddr = smem_u32(sA) + wid * 4096 + (lane & 15) * 128;
    const u32 chb   = (lane >> 4);

    #pragma unroll
    for (int mt = 0; mt < 2; ++mt) {
        u32 Ah[2][4], Al[2][4];
        const u32 tb = aAddr + mt * 2048;
        LDSM_X4(Ah[0][0], Ah[0][1], Ah[0][2], Ah[0][3], tb + (((chb + 0) ^ sw) << 4));
        LDSM_X4(Ah[1][0], Ah[1][1], Ah[1][2], Ah[1][3], tb + (((chb + 2) ^ sw) << 4));
        LDSM_X4(Al[0][0], Al[0][1], Al[0][2], Al[0][3], tb + (((chb + 4) ^ sw) << 4));
        LDSM_X4(Al[1][0], Al[1][1], Al[1][2], Al[1][3], tb + (((chb + 6) ^ sw) << 4));

        #pragma unroll
        for (int nt = 0; nt < 4; ++nt) {
            uint4 BH = sB[(l * 4 + nt) * 32 + lane];
            uint4 BL = sB[512 + (l * 4 + nt) * 32 + lane];
            float c[4] = {0.0f, 0.0f, 0.0f, 0.0f};
            mma_bf16(c, Ah[0], BH.x, BH.y);
            mma_bf16(c, Ah[1], BH.z, BH.w);
            mma_bf16(c, Ah[0], BL.x, BL.y);
            mma_bf16(c, Ah[1], BL.z, BL.w);
            mma_bf16(c, Al[0], BH.x, BH.y);
            mma_bf16(c, Al[1], BH.z, BH.w);

            const int m0 = 2 * mt, m1 = 2 * mt + 1;
            float f0 = (nt == 0) ? 1.0f : (nt == 1) ? cnt1[m0]
                     : (nt == 2) ? cnt2[m0] : cnt3[m0];
            float f1 = (nt == 0) ? 1.0f : (nt == 1) ? cnt1[m1]
                     : (nt == 2) ? cnt2[m1] : cnt3[m1];
            float p0 = pb[m0] * f0;
            float p1 = pb[m1] * f1;
            dpart[m0] += c[0] * p0 + c[1] * (p0 * s4m[m0]);
            dpart[m1] += c[2] * p1 + c[3] * (p1 * s4m[m1]);
        }
    }

    // ---- reduce: quad (h coverage), then lin_w dot across d-groups ----
    #pragma unroll
    for (int m = 0; m < 4; ++m) {
        dpart[m] += __shfl_xor_sync(0xffffffffu, dpart[m], 1);
        dpart[m] += __shfl_xor_sync(0xffffffffu, dpart[m], 2);
    }
    const float db = dend_b[l];
    float v = 0.0f;
    #pragma unroll
    for (int m = 0; m < 4; ++m)
        v = fmaf(dpart[m] + db, lin_w[l * ND + g + 8 * m], v);
    v += __shfl_xor_sync(0xffffffffu, v, 4);
    v += __shfl_xor_sync(0xffffffffu, v, 8);
    v += __shfl_xor_sync(0xffffffffu, v, 16);

    __syncthreads();   // all smem reads done before sfin overlays sA
    if (lane == 0) sfin[bl][l] = (v + lin_b[l]) * final_w[l];
    __syncthreads();

    if (tid < 2) {
        int bb = blockIdx.x * 2 + tid;
        float fin = sfin[tid][0] + sfin[tid][1] + sfin[tid][2] + sfin[tid][3]
                  + final_b[0];
        out[bb] = 1.0f / (1.0f + __expf(-ks[0] * fin));
    }
}

extern "C" void kernel_launch(void* const* d_in, const int* in_sizes, int n_in,
                              void* d_out, int out_size) {
    const float* x       = (const float*)d_in[0];
    const float* k       = (const float*)d_in[1];
    const float* w       = (const float*)d_in[2];
    const float* q       = (const float*)d_in[3];
    const float* dend_w  = (const float*)d_in[4];
    const float* dend_b  = (const float*)d_in[5];
    const float* lin_w   = (const float*)d_in[6];
    const float* lin_b   = (const float*)d_in[7];
    const float* final_w = (const float*)d_in[8];
    const float* final_b = (const float*)d_in[9];
    const float* ks      = (const float*)d_in[10];
    float* out = (float*)d_out;

    main_kernel<<<NB / 2, 256>>>(x, k, w, q, dend_w, dend_b,
                                 lin_w, lin_b, final_w, final_b, ks, out);
}

// round 17
// speedup vs baseline: 1.0953x; 1.0953x over previous
#include <cuda_runtime.h>
#include <cuda_bf16.h>

#define NS 10
#define ND 32
#define NL 4
#define NB 1024

typedef unsigned int u32;

// Prepacked B fragments: g_Bpk[l][nt][lane][term] = uint4(b0_kt0, b1_kt0, b0_kt1, b1_kt1)
// term 0 = bf16 hi, term 1 = bf16 residual (val - f32(hi)).
__device__ __align__(16) uint4 g_Bpk[NL][4][32][2];

// cvt.rn.bf16x2.f32 d, a, b : upper16 = cvt(a), lower16 = cvt(b)
__device__ __forceinline__ u32 cvt2(float lo, float hi) {
    u32 r;
    asm("cvt.rn.bf16x2.f32 %0, %1, %2;" : "=r"(r) : "f"(hi), "f"(lo));
    return r;
}
__device__ __forceinline__ float lo_f(u32 p) { return __uint_as_float(p << 16); }
__device__ __forceinline__ float hi_f(u32 p) { return __uint_as_float(p & 0xffff0000u); }

__device__ __forceinline__ void mma_bf16(float* c, const u32* a, u32 b0, u32 b1) {
    asm volatile("mma.sync.aligned.m16n8k16.row.col.f32.bf16.bf16.f32 "
                 "{%0,%1,%2,%3}, {%4,%5,%6,%7}, {%8,%9}, {%0,%1,%2,%3};"
                 : "+f"(c[0]), "+f"(c[1]), "+f"(c[2]), "+f"(c[3])
                 : "r"(a[0]), "r"(a[1]), "r"(a[2]), "r"(a[3]), "r"(b0), "r"(b1));
}
#define LDSM_X4(r0, r1, r2, r3, addr) \
    asm volatile("ldmatrix.sync.aligned.m8n8.x4.shared.b16 {%0,%1,%2,%3}, [%4];" \
                 : "=r"(r0), "=r"(r1), "=r"(r2), "=r"(r3) : "r"(addr))

__device__ __forceinline__ u32 smem_u32(const void* p) {
    u32 a;
    asm("{ .reg .u64 t; cvta.to.shared.u64 t, %1; cvt.u32.u64 %0, t; }"
        : "=r"(a) : "l"(p));
    return a;
}

// ============================================================
// Prep: pack DW_l (32x32, dwpad[0]=0) into per-lane mma B fragments.
// B[n][k] = DW[h = 8*nt + g][lo = k + 16*kt];  b0 = (k=2tq, 2tq+1), b1 = (+8,+9).
// ============================================================
__global__ void prep_kernel(const float* __restrict__ dend_w) {
    int l    = blockIdx.x;
    int nt   = threadIdx.x >> 5;
    int lane = threadIdx.x & 31;
    int tq = lane & 3;
    int h = nt * 8 + (lane >> 2);

    float v[8];
    #pragma unroll
    for (int kt = 0; kt < 2; ++kt)
        #pragma unroll
        for (int j = 0; j < 4; ++j) {
            int col = 2 * tq + (j & 1) + 8 * (j >> 1) + 16 * kt;
            int vv  = 32 * h + col;          // v index into padded dend_w
            v[kt * 4 + j] = vv ? dend_w[l * 1023 + vv - 1] : 0.0f;
        }
    u32 hi[4], lo[4];
    #pragma unroll
    for (int p = 0; p < 4; ++p) {
        hi[p] = cvt2(v[2 * p], v[2 * p + 1]);
        lo[p] = cvt2(v[2 * p] - lo_f(hi[p]), v[2 * p + 1] - hi_f(hi[p]));
    }
    g_Bpk[l][nt][lane][0] = make_uint4(hi[0], hi[1], hi[2], hi[3]);
    g_Bpk[l][nt][lane][1] = make_uint4(lo[0], lo[1], lo[2], lo[3]);
}

// ============================================================
// Main: block = 256 threads = 8 warps = (2 batch) x (4 layers).
// Warp: 32 rows (d = lane) of one (b, l). C[row, h] = Plo @ DW^T via mma.sync,
// then dend = Phi-dot on C fragments, warp/block reduce, sigmoid -> out.
// B fragments are prefetched into registers at kernel entry (hidden under
// the sigmoid/Plo/cvt setup math). A staged in smem, XOR-16B swizzle + LDSM.
// ============================================================
__global__ __launch_bounds__(256)
void main_kernel(const float* __restrict__ x,
                 const float* __restrict__ k,
                 const float* __restrict__ w,
                 const float* __restrict__ q,
                 const float* __restrict__ dend_b,
                 const float* __restrict__ lin_w,
                 const float* __restrict__ lin_b,
                 const float* __restrict__ final_w,
                 const float* __restrict__ final_b,
                 const float* __restrict__ ks,
                 float* __restrict__ out)
{
    __shared__ __align__(16) unsigned char sA[8 * 4096];   // 32 KB, 128B/row
    __shared__ float sfin[2][NL];

    const int tid  = threadIdx.x;
    const int wid  = tid >> 5, lane = tid & 31;
    const int l    = wid & 3,  bl   = wid >> 2;
    const int b    = blockIdx.x * 2 + bl;
    const int g    = lane >> 2, tq = lane & 3;
    const int sw   = lane & 7;

    // ---- early B prefetch (8x LDG.128, consumed after the barrier) ----
    uint4 BH[4], BL[4];
    #pragma unroll
    for (int nt = 0; nt < 4; ++nt) {
        BH[nt] = g_Bpk[l][nt][lane][0];
        BL[nt] = g_Bpk[l][nt][lane][1];
    }

    // ---- s_i = sigmoid(k*(w*x - q)), row = (l, d=lane); float2 loads ----
    float s[NS];
    {
        const float2* x2 = reinterpret_cast<const float2*>(x) + b * 5;
        const float2* k2 = reinterpret_cast<const float2*>(k) + (l * ND + lane) * 5;
        const float2* w2 = reinterpret_cast<const float2*>(w) + (l * ND + lane) * 5;
        const float2* q2 = reinterpret_cast<const float2*>(q) + (l * ND + lane) * 5;
        #pragma unroll
        for (int j = 0; j < 5; ++j) {
            float2 xx = x2[j], kk = k2[j], ww = w2[j], qq = q2[j];
            float z0 = kk.x * (ww.x * xx.x - qq.x);
            float z1 = kk.y * (ww.y * xx.y - qq.y);
            s[2 * j]     = 1.0f / (1.0f + __expf(-z0));
            s[2 * j + 1] = 1.0f / (1.0f + __expf(-z1));
        }
    }

    // ---- Plo subset products (bit p of lo -> s[9-p]) ----
    float Plo[32];
    Plo[0] = 1.0f;
    #pragma unroll
    for (int bit = 0; bit < 5; ++bit) {
        const float sv = s[9 - bit];
        #pragma unroll
        for (int u = 0; u < (1 << bit); ++u)
            Plo[(1 << bit) + u] = Plo[u] * sv;
    }

    // ---- stage A row: 128B/row, 16B chunks XOR-swizzled by (row & 7) ----
    // chunks 0..3 = bf16 hi pairs, 4..7 = residual lo pairs.
    {
        u32 hi[16], lo[16];
        #pragma unroll
        for (int c = 0; c < 16; ++c)
            hi[c] = cvt2(Plo[2 * c], Plo[2 * c + 1]);
        #pragma unroll
        for (int c = 0; c < 16; ++c)
            lo[c] = cvt2(Plo[2 * c] - lo_f(hi[c]), Plo[2 * c + 1] - hi_f(hi[c]));
        unsigned char* rb = sA + wid * 4096 + lane * 128;
        #pragma unroll
        for (int c = 0; c < 4; ++c)
            *reinterpret_cast<uint4*>(rb + ((c ^ sw) << 4)) =
                make_uint4(hi[4 * c], hi[4 * c + 1], hi[4 * c + 2], hi[4 * c + 3]);
        #pragma unroll
        for (int c = 0; c < 4; ++c)
            *reinterpret_cast<uint4*>(rb + (((c + 4) ^ sw) << 4)) =
                make_uint4(lo[4 * c], lo[4 * c + 1], lo[4 * c + 2], lo[4 * c + 3]);
    }

    // ---- Phi factors for the 4 C-fragment rows (g, g+8, g+16, g+24) ----
    // h = 8*nt + 2*tq + e : bit0=e->s4, bits1-2=tq->s3,s2, bits3-4=nt->s1,s0
    float pb[4], s4m[4], cnt1[4], cnt2[4], cnt3[4];
    #pragma unroll
    for (int m = 0; m < 4; ++m) {
        int src = g + 8 * m;
        float a0 = __shfl_sync(0xffffffffu, s[0], src);
        float a1 = __shfl_sync(0xffffffffu, s[1], src);
        float a2 = __shfl_sync(0xffffffffu, s[2], src);
        float a3 = __shfl_sync(0xffffffffu, s[3], src);
        s4m[m]   = __shfl_sync(0xffffffffu, s[4], src);
        pb[m] = ((tq & 1) ? a3 : 1.0f) * ((tq & 2) ? a2 : 1.0f);
        cnt1[m] = a1; cnt2[m] = a0; cnt3[m] = a0 * a1;
    }
    __syncthreads();   // A rows visible

    // ---- mma mainloop ----
    float dpart[4] = {0.0f, 0.0f, 0.0f, 0.0f};
    const u32 aAddr = smem_u32(sA) + wid * 4096 + (lane & 15) * 128;
    const u32 chb   = (lane >> 4);

    #pragma unroll
    for (int mt = 0; mt < 2; ++mt) {
        u32 Ah[2][4], Al[2][4];
        const u32 tb = aAddr + mt * 2048;
        LDSM_X4(Ah[0][0], Ah[0][1], Ah[0][2], Ah[0][3], tb + (((chb + 0) ^ sw) << 4));
        LDSM_X4(Ah[1][0], Ah[1][1], Ah[1][2], Ah[1][3], tb + (((chb + 2) ^ sw) << 4));
        LDSM_X4(Al[0][0], Al[0][1], Al[0][2], Al[0][3], tb + (((chb + 4) ^ sw) << 4));
        LDSM_X4(Al[1][0], Al[1][1], Al[1][2], Al[1][3], tb + (((chb + 6) ^ sw) << 4));

        #pragma unroll
        for (int nt = 0; nt < 4; ++nt) {
            float c[4] = {0.0f, 0.0f, 0.0f, 0.0f};
            mma_bf16(c, Ah[0], BH[nt].x, BH[nt].y);
            mma_bf16(c, Ah[1], BH[nt].z, BH[nt].w);
            mma_bf16(c, Ah[0], BL[nt].x, BL[nt].y);
            mma_bf16(c, Ah[1], BL[nt].z, BL[nt].w);
            mma_bf16(c, Al[0], BH[nt].x, BH[nt].y);
            mma_bf16(c, Al[1], BH[nt].z, BH[nt].w);

            const int m0 = 2 * mt, m1 = 2 * mt + 1;
            float f0 = (nt == 0) ? 1.0f : (nt == 1) ? cnt1[m0]
                     : (nt == 2) ? cnt2[m0] : cnt3[m0];
            float f1 = (nt == 0) ? 1.0f : (nt == 1) ? cnt1[m1]
                     : (nt == 2) ? cnt2[m1] : cnt3[m1];
            float p0 = pb[m0] * f0;
            float p1 = pb[m1] * f1;
            dpart[m0] += c[0] * p0 + c[1] * (p0 * s4m[m0]);
            dpart[m1] += c[2] * p1 + c[3] * (p1 * s4m[m1]);
        }
    }

    // ---- reduce: quad (h coverage), then lin_w dot across d-groups ----
    #pragma unroll
    for (int m = 0; m < 4; ++m) {
        dpart[m] += __shfl_xor_sync(0xffffffffu, dpart[m], 1);
        dpart[m] += __shfl_xor_sync(0xffffffffu, dpart[m], 2);
    }
    const float db = dend_b[l];
    float v = 0.0f;
    #pragma unroll
    for (int m = 0; m < 4; ++m)
        v = fmaf(dpart[m] + db, lin_w[l * ND + g + 8 * m], v);
    v += __shfl_xor_sync(0xffffffffu, v, 4);
    v += __shfl_xor_sync(0xffffffffu, v, 8);
    v += __shfl_xor_sync(0xffffffffu, v, 16);
    if (lane == 0) sfin[bl][l] = (v + lin_b[l]) * final_w[l];
    __syncthreads();

    if (tid < 2) {
        int bb = blockIdx.x * 2 + tid;
        float fin = sfin[tid][0] + sfin[tid][1] + sfin[tid][2] + sfin[tid][3]
                  + final_b[0];
        out[bb] = 1.0f / (1.0f + __expf(-ks[0] * fin));
    }
}

extern "C" void kernel_launch(void* const* d_in, const int* in_sizes, int n_in,
                              void* d_out, int out_size) {
    const float* x       = (const float*)d_in[0];
    const float* k       = (const float*)d_in[1];
    const float* w       = (const float*)d_in[2];
    const float* q       = (const float*)d_in[3];
    const float* dend_w  = (const float*)d_in[4];
    const float* dend_b  = (const float*)d_in[5];
    const float* lin_w   = (const float*)d_in[6];
    const float* lin_b   = (const float*)d_in[7];
    const float* final_w = (const float*)d_in[8];
    const float* final_b = (const float*)d_in[9];
    const float* ks      = (const float*)d_in[10];
    float* out = (float*)d_out;

    prep_kernel<<<NL, 128>>>(dend_w);
    main_kernel<<<NB / 2, 256>>>(x, k, w, q, dend_b,
                                 lin_w, lin_b, final_w, final_b, ks, out);
}